// round 12
// baseline (speedup 1.0000x reference)
#include <cuda_runtime.h>
#include <cuda_fp16.h>
#include <cstdint>
#include <cstddef>

#define DINL __device__ __forceinline__

// ---------------- problem constants ----------------
constexpr int MDIM = 8192;   // B*S
constexpr int NDIM = 4096;   // OUT_FEATURES
constexpr int KDIM = 4096;   // IN_FEATURES

// ---------------- GEMM tiling ----------------
constexpr int BM = 128;
constexpr int BN = 256;
constexpr int BK = 128;                      // halves; stored as 2 sub-tiles of 64
constexpr int STAGES = 2;
constexpr int NITER = KDIM / BK;             // 32
constexpr int THREADS = 512;                 // 16 warps: 2 (M) x 8 (N), warp tile 64x32

constexpr uint32_t A_SUB = BM * 64 * 2;      // 16 KB per k-half
constexpr uint32_t B_SUB = BN * 64 * 2;      // 32 KB per k-half
constexpr uint32_t A_TOT = 2 * A_SUB;        // 32 KB
constexpr uint32_t B_TOT = 2 * B_SUB;        // 64 KB
constexpr uint32_t STAGE_BYTES = A_TOT + B_TOT;          // 96 KB
constexpr uint32_t SMEM_BYTES  = STAGES * STAGE_BYTES;   // 192 KB

// ---------------- scratch (device globals: allocation-rule-safe) ----------------
__device__ __align__(1024) __half g_Xh[(size_t)MDIM * KDIM];  // x fp16, [M,K] row-major
__device__ __align__(1024) __half g_Wt[(size_t)NDIM * KDIM];  // W^T fp16, [N,K] row-major

// ---------------- PTX helpers ----------------
DINL uint32_t s2u(const void* p) {
    uint32_t a;
    asm("{ .reg .u64 t; cvta.to.shared.u64 t, %1; cvt.u32.u64 %0, t; }" : "=r"(a) : "l"(p));
    return a;
}
DINL void cp16(uint32_t saddr, const void* gaddr) {
    asm volatile("cp.async.cg.shared.global [%0], [%1], 16;" :: "r"(saddr), "l"(gaddr));
}
DINL void cp_commit() { asm volatile("cp.async.commit_group;" ::: "memory"); }
template <int N> DINL void cp_wait() {
    asm volatile("cp.async.wait_group %0;" :: "n"(N) : "memory");
}
DINL void ldsm4(uint32_t& r0, uint32_t& r1, uint32_t& r2, uint32_t& r3, uint32_t a) {
    asm volatile("ldmatrix.sync.aligned.m8n8.x4.shared.b16 {%0,%1,%2,%3}, [%4];"
                 : "=r"(r0), "=r"(r1), "=r"(r2), "=r"(r3) : "r"(a));
}
DINL void mma16816(float* d, const uint32_t* a, const uint32_t* b) {
    asm volatile(
        "mma.sync.aligned.m16n8k16.row.col.f32.f16.f16.f32 "
        "{%0,%1,%2,%3}, {%4,%5,%6,%7}, {%8,%9}, {%0,%1,%2,%3};"
        : "+f"(d[0]), "+f"(d[1]), "+f"(d[2]), "+f"(d[3])
        : "r"(a[0]), "r"(a[1]), "r"(a[2]), "r"(a[3]), "r"(b[0]), "r"(b[1]));
}

// ---------------- kernel 1: fused pre-pass ----------------
// Blocks [0, CVT_BLOCKS): x fp32 -> fp16 (2 x float4 per thread).
// Blocks [CVT_BLOCKS, CVT_BLOCKS + DQ_BLOCKS): GPTQ dequant + transpose.
// The two phases are independent and both DRAM-bound; one launch lets them
// overlap instead of serializing under graph capture.
constexpr size_t   CVT_QUADS  = (size_t)MDIM * KDIM / 4;            // float4 count
constexpr unsigned CVT_BLOCKS = (unsigned)(CVT_QUADS / 2 / 256);    // 16384
constexpr unsigned DQ_KB      = KDIM / 64;                          // 64
constexpr unsigned DQ_BLOCKS  = DQ_KB * (NDIM / 64);                // 4096

__global__ void __launch_bounds__(256)
k_prep(const float4* __restrict__ x, __half2* __restrict__ xh,
       const int* __restrict__ qw, const int* __restrict__ qz,
       const float* __restrict__ sc, __half* __restrict__ wt) {
    const int t = threadIdx.x;

    if (blockIdx.x < CVT_BLOCKS) {
        // ---- phase A: fp32 -> fp16 convert ----
        size_t i = (size_t)blockIdx.x * 256 + t;
        float4 v0 = x[i];
        float4 v1 = x[i + CVT_QUADS / 2];
        xh[2 * i]                       = __floats2half2_rn(v0.x, v0.y);
        xh[2 * i + 1]                   = __floats2half2_rn(v0.z, v0.w);
        xh[2 * (i + CVT_QUADS / 2)]     = __floats2half2_rn(v1.x, v1.y);
        xh[2 * (i + CVT_QUADS / 2) + 1] = __floats2half2_rn(v1.z, v1.w);
        return;
    }

    // ---- phase B: GPTQ dequant + transpose ----
    // qweight [K/8, N] int32 (8 nibbles along K), qzeros [G, N/8] int32 (8
    // nibbles along N), scales [G, N] fp32.
    // Output: g_Wt[n][k] = scales[g][n] * (q - (z+1)) in fp16.
    const unsigned bid = blockIdx.x - CVT_BLOCKS;
    const int k0 = (int)(bid % DQ_KB) * 64;
    const int n0 = (int)(bid / DQ_KB) * 64;
    const int g  = k0 >> 7;                 // GROUPSIZE=128: 64-wide k-tile inside one group

    __shared__ int   sQ[8][64];
    __shared__ float sS[64];
    __shared__ float sZ[64];

    for (int i = t; i < 512; i += 256) {
        int r = i >> 6, c = i & 63;
        sQ[r][c] = qw[(size_t)(k0 / 8 + r) * NDIM + n0 + c];
    }
    if (t < 64) {
        int n = n0 + t;
        sS[t] = sc[(size_t)g * NDIM + n];
        unsigned z = ((unsigned)qz[(size_t)g * (NDIM / 8) + (n >> 3)] >> ((n & 7) * 4)) & 0xFu;
        sZ[t] = (float)(z + 1u);
    }
    __syncthreads();

    int ni = t >> 2, kq = t & 3;            // 64 n-rows x 4 k-quarters of 16
    float s = sS[ni], zp = sZ[ni];
    __half2 o[8];
#pragma unroll
    for (int j = 0; j < 2; j++) {
        unsigned packed = (unsigned)sQ[kq * 2 + j][ni];
#pragma unroll
        for (int b = 0; b < 4; b++) {
            float q0 = (float)(packed & 0xFu); packed >>= 4;
            float q1 = (float)(packed & 0xFu); packed >>= 4;
            o[j * 4 + b] = __floats2half2_rn(s * (q0 - zp), s * (q1 - zp));
        }
    }
    float4* dst = (float4*)(wt + (size_t)(n0 + ni) * KDIM + k0 + kq * 16);
    dst[0] = *(float4*)&o[0];
    dst[1] = *(float4*)&o[4];
}

// ---------------- kernel 2: 2-stage BK=128 HMMA GEMM + bias ----------------
// A = g_Xh [M,K] row-major, B = g_Wt [N,K] row-major ("col" operand), C fp32.
// Stage layout: [A(k0:64) 16K][A(k64:128) 16K][B(k0:64) 32K][B(k64:128) 32K].
// Each sub-tile: rows of 128B (8 x 16B chunks), chunk ^= (row & 7).
extern __shared__ __align__(1024) uint8_t g_smem[];

DINL void issue_stage(uint32_t sb, int stage, int kblk,
                      const __half* gA0, const __half* gB0,
                      int arow0, uint32_t asw) {
    const uint32_t sa = sb + (uint32_t)stage * STAGE_BYTES;
#pragma unroll
    for (int sub = 0; sub < 2; ++sub) {
        const uint32_t sA = sa + (uint32_t)sub * A_SUB + (uint32_t)arow0 * 128 + asw;
        const uint32_t sB = sa + A_TOT + (uint32_t)sub * B_SUB + (uint32_t)arow0 * 128 + asw;
        const __half* ga = gA0 + kblk * BK + sub * 64;
        const __half* gb = gB0 + kblk * BK + sub * 64;
        // 512 threads: A sub-tile 128 rows (2 x 64), B sub-tile 256 rows (4 x 64)
#pragma unroll
        for (int j = 0; j < 2; ++j)
            cp16(sA + j * 64 * 128, ga + (size_t)j * 64 * KDIM);
#pragma unroll
        for (int j = 0; j < 4; ++j)
            cp16(sB + j * 64 * 128, gb + (size_t)j * 64 * KDIM);
    }
    cp_commit();
}

__global__ void __launch_bounds__(THREADS, 1)
k_gemm(const __half* __restrict__ A, const __half* __restrict__ Bw,
       const float* __restrict__ bias, float* __restrict__ out) {
    const uint32_t sb = s2u(g_smem);
    const int tid  = threadIdx.x;
    const int wid  = tid >> 5;
    const int lane = tid & 31;
    const int m0 = blockIdx.y * BM;
    const int n0 = blockIdx.x * BN;

    const int wr = wid >> 3;       // 0..1  (M) -> 64 rows
    const int wc = wid & 7;        // 0..7  (N) -> 32 cols

    // cp.async thread mapping: 512 threads, 8 chunks/row; rows step by 64 (row&7 const)
    const int arow0 = tid >> 3;          // 0..63
    const int ach   = tid & 7;
    const uint32_t asw = (uint32_t)((ach ^ (arow0 & 7)) * 16);

    const __half* gA0 = A  + (size_t)(m0 + arow0) * KDIM + ach * 8;
    const __half* gB0 = Bw + (size_t)(n0 + arow0) * KDIM + ach * 8;

    // ---- prologue: fill STAGES-1 = 1 stage ----
#pragma unroll
    for (int s = 0; s < STAGES - 1; ++s)
        issue_stage(sb, s, s, gA0, gB0, arow0, asw);

    // ---- ldmatrix per-lane addressing ----
    const int a_r = (lane & 15);
    const int a_c = (lane >> 4);
    const int b_r = (lane & 7) + ((lane >> 4) << 3);
    const int b_c = (lane >> 3) & 1;

    float acc[4][4][4];
#pragma unroll
    for (int mi = 0; mi < 4; ++mi)
#pragma unroll
        for (int ni = 0; ni < 4; ++ni)
#pragma unroll
            for (int e = 0; e < 4; ++e) acc[mi][ni][e] = 0.f;

    for (int it = 0; it < NITER; ++it) {
        cp_wait<0>();               // all outstanding prefetches (prev iter's stage)
        __syncthreads();

        if (it + STAGES - 1 < NITER)
            issue_stage(sb, (it + STAGES - 1) % STAGES, it + STAGES - 1,
                        gA0, gB0, arow0, asw);

        const uint32_t sa = sb + (uint32_t)(it % STAGES) * STAGE_BYTES;

#pragma unroll
        for (int ks8 = 0; ks8 < 8; ++ks8) {
            const int sub = ks8 >> 2;
            const int ks  = ks8 & 3;
            const uint32_t aBase = sa + (uint32_t)sub * A_SUB;
            const uint32_t bBase = sa + A_TOT + (uint32_t)sub * B_SUB;

            uint32_t af[4][4], bf[2][4];
#pragma unroll
            for (int mi = 0; mi < 4; ++mi) {
                int row = wr * 64 + mi * 16 + a_r;
                int ch  = (ks * 2 + a_c) ^ (row & 7);
                ldsm4(af[mi][0], af[mi][1], af[mi][2], af[mi][3],
                      aBase + (uint32_t)row * 128 + (uint32_t)ch * 16);
            }
#pragma unroll
            for (int nj = 0; nj < 2; ++nj) {
                int row = wc * 32 + nj * 16 + b_r;
                int ch  = (ks * 2 + b_c) ^ (row & 7);
                ldsm4(bf[nj][0], bf[nj][1], bf[nj][2], bf[nj][3],
                      bBase + (uint32_t)row * 128 + (uint32_t)ch * 16);
            }
#pragma unroll
            for (int mi = 0; mi < 4; ++mi)
#pragma unroll
                for (int ni = 0; ni < 4; ++ni)
                    mma16816(acc[mi][ni], af[mi], &bf[ni >> 1][(ni & 1) * 2]);
        }
    }

    // ---- epilogue: bias + fp32 store ----
    const int mrow = lane >> 2;
    const int ncol = (lane & 3) * 2;
#pragma unroll
    for (int mi = 0; mi < 4; ++mi) {
#pragma unroll
        for (int ni = 0; ni < 4; ++ni) {
            int n = n0 + wc * 32 + ni * 8 + ncol;
            float2 b2 = *(const float2*)(bias + n);
            size_t m = (size_t)m0 + wr * 64 + mi * 16 + mrow;
            float2 v0 = { acc[mi][ni][0] + b2.x, acc[mi][ni][1] + b2.y };
            float2 v1 = { acc[mi][ni][2] + b2.x, acc[mi][ni][3] + b2.y };
            *(float2*)(out + m * NDIM + n)       = v0;
            *(float2*)(out + (m + 8) * NDIM + n) = v1;
        }
    }
}

// ---------------- host ----------------
extern "C" void kernel_launch(void* const* d_in, const int* in_sizes, int n_in,
                              void* d_out, int out_size) {
    (void)in_sizes; (void)n_in; (void)out_size;
    const float* x    = (const float*)d_in[0];
    const int*   qw   = (const int*)d_in[1];
    const int*   qz   = (const int*)d_in[2];
    const float* sc   = (const float*)d_in[3];
    const float* bias = (const float*)d_in[4];
    float* out = (float*)d_out;

    void* xh_p = nullptr; void* wt_p = nullptr;
    cudaGetSymbolAddress(&xh_p, g_Xh);
    cudaGetSymbolAddress(&wt_p, g_Wt);

    // 1) fused pre-pass: x->fp16 convert + GPTQ dequant/transpose (overlapped)
    k_prep<<<CVT_BLOCKS + DQ_BLOCKS, 256>>>(
        (const float4*)x, (__half2*)xh_p, qw, qz, sc, (__half*)wt_p);
    // 2) 2-stage BK=128 HMMA GEMM + bias (16 warps)
    cudaFuncSetAttribute(k_gemm, cudaFuncAttributeMaxDynamicSharedMemorySize, SMEM_BYTES);
    k_gemm<<<dim3(NDIM / BN, MDIM / BM), THREADS, SMEM_BYTES>>>(
        (const __half*)xh_p, (const __half*)wt_p, bias, out);
}

// round 15
// speedup vs baseline: 1.0139x; 1.0139x over previous
#include <cuda_runtime.h>
#include <cuda_fp16.h>
#include <cstdint>
#include <cstddef>

#define DINL __device__ __forceinline__

// ---------------- problem constants ----------------
constexpr int MDIM = 8192;   // B*S
constexpr int NDIM = 4096;   // OUT_FEATURES
constexpr int KDIM = 4096;   // IN_FEATURES

// ---------------- GEMM tiling (sized for 2 CTAs/SM) ----------------
constexpr int BM = 128;
constexpr int BN = 128;
constexpr int BK = 64;                       // halves; 128 B per smem row
constexpr int STAGES = 2;
constexpr int NITER = KDIM / BK;             // 64
constexpr int THREADS = 256;                 // 8 warps: 2 (M) x 4 (N), warp tile 64x32

constexpr uint32_t A_ST = BM * BK * 2;       // 16 KB
constexpr uint32_t B_ST = BN * BK * 2;       // 16 KB
constexpr uint32_t STAGE_BYTES = A_ST + B_ST;            // 32 KB
constexpr uint32_t SMEM_BYTES  = STAGES * STAGE_BYTES;   // 64 KB -> 2 CTAs/SM

// ---------------- scratch (device globals: allocation-rule-safe) ----------------
__device__ __align__(1024) __half g_Xh[(size_t)MDIM * KDIM];  // x fp16, [M,K] row-major
__device__ __align__(1024) __half g_Wt[(size_t)NDIM * KDIM];  // W^T fp16, [N,K] row-major

// ---------------- PTX helpers ----------------
DINL uint32_t s2u(const void* p) {
    uint32_t a;
    asm("{ .reg .u64 t; cvta.to.shared.u64 t, %1; cvt.u32.u64 %0, t; }" : "=r"(a) : "l"(p));
    return a;
}
DINL void cp16(uint32_t saddr, const void* gaddr) {
    asm volatile("cp.async.cg.shared.global [%0], [%1], 16;" :: "r"(saddr), "l"(gaddr));
}
DINL void cp_commit() { asm volatile("cp.async.commit_group;" ::: "memory"); }
template <int N> DINL void cp_wait() {
    asm volatile("cp.async.wait_group %0;" :: "n"(N) : "memory");
}
DINL void ldsm4(uint32_t& r0, uint32_t& r1, uint32_t& r2, uint32_t& r3, uint32_t a) {
    asm volatile("ldmatrix.sync.aligned.m8n8.x4.shared.b16 {%0,%1,%2,%3}, [%4];"
                 : "=r"(r0), "=r"(r1), "=r"(r2), "=r"(r3) : "r"(a));
}
DINL void mma16816(float* d, const uint32_t* a, const uint32_t* b) {
    asm volatile(
        "mma.sync.aligned.m16n8k16.row.col.f32.f16.f16.f32 "
        "{%0,%1,%2,%3}, {%4,%5,%6,%7}, {%8,%9}, {%0,%1,%2,%3};"
        : "+f"(d[0]), "+f"(d[1]), "+f"(d[2]), "+f"(d[3])
        : "r"(a[0]), "r"(a[1]), "r"(a[2]), "r"(a[3]), "r"(b[0]), "r"(b[1]));
}

// ---------------- kernel 1: fused pre-pass ----------------
// Blocks [0, CVT_BLOCKS): x fp32 -> fp16 (2 x float4 per thread).
// Blocks [CVT_BLOCKS, CVT_BLOCKS + DQ_BLOCKS): GPTQ dequant + transpose.
constexpr size_t   CVT_QUADS  = (size_t)MDIM * KDIM / 4;            // float4 count
constexpr unsigned CVT_BLOCKS = (unsigned)(CVT_QUADS / 2 / 256);    // 16384
constexpr unsigned DQ_KB      = KDIM / 64;                          // 64
constexpr unsigned DQ_BLOCKS  = DQ_KB * (NDIM / 64);                // 4096

__global__ void __launch_bounds__(256)
k_prep(const float4* __restrict__ x, __half2* __restrict__ xh,
       const int* __restrict__ qw, const int* __restrict__ qz,
       const float* __restrict__ sc, __half* __restrict__ wt) {
    const int t = threadIdx.x;

    if (blockIdx.x < CVT_BLOCKS) {
        // ---- phase A: fp32 -> fp16 convert ----
        size_t i = (size_t)blockIdx.x * 256 + t;
        float4 v0 = x[i];
        float4 v1 = x[i + CVT_QUADS / 2];
        xh[2 * i]                       = __floats2half2_rn(v0.x, v0.y);
        xh[2 * i + 1]                   = __floats2half2_rn(v0.z, v0.w);
        xh[2 * (i + CVT_QUADS / 2)]     = __floats2half2_rn(v1.x, v1.y);
        xh[2 * (i + CVT_QUADS / 2) + 1] = __floats2half2_rn(v1.z, v1.w);
        return;
    }

    // ---- phase B: GPTQ dequant + transpose ----
    // qweight [K/8, N] int32 (8 nibbles along K), qzeros [G, N/8] int32 (8
    // nibbles along N), scales [G, N] fp32.
    // Output: g_Wt[n][k] = scales[g][n] * (q - (z+1)) in fp16.
    const unsigned bid = blockIdx.x - CVT_BLOCKS;
    const int k0 = (int)(bid % DQ_KB) * 64;
    const int n0 = (int)(bid / DQ_KB) * 64;
    const int g  = k0 >> 7;                 // GROUPSIZE=128: 64-wide k-tile inside one group

    __shared__ int   sQ[8][64];
    __shared__ float sS[64];
    __shared__ float sZ[64];

    for (int i = t; i < 512; i += 256) {
        int r = i >> 6, c = i & 63;
        sQ[r][c] = qw[(size_t)(k0 / 8 + r) * NDIM + n0 + c];
    }
    if (t < 64) {
        int n = n0 + t;
        sS[t] = sc[(size_t)g * NDIM + n];
        unsigned z = ((unsigned)qz[(size_t)g * (NDIM / 8) + (n >> 3)] >> ((n & 7) * 4)) & 0xFu;
        sZ[t] = (float)(z + 1u);
    }
    __syncthreads();

    int ni = t >> 2, kq = t & 3;            // 64 n-rows x 4 k-quarters of 16
    float s = sS[ni], zp = sZ[ni];
    __half2 o[8];
#pragma unroll
    for (int j = 0; j < 2; j++) {
        unsigned packed = (unsigned)sQ[kq * 2 + j][ni];
#pragma unroll
        for (int b = 0; b < 4; b++) {
            float q0 = (float)(packed & 0xFu); packed >>= 4;
            float q1 = (float)(packed & 0xFu); packed >>= 4;
            o[j * 4 + b] = __floats2half2_rn(s * (q0 - zp), s * (q1 - zp));
        }
    }
    float4* dst = (float4*)(wt + (size_t)(n0 + ni) * KDIM + k0 + kq * 16);
    dst[0] = *(float4*)&o[0];
    dst[1] = *(float4*)&o[4];
}

// ---------------- kernel 2: 2-stage HMMA GEMM, 2 CTAs/SM ----------------
// A = g_Xh [M,K] row-major, B = g_Wt [N,K] row-major ("col" operand), C fp32.
// smem per stage: A then B; rows of 128B (8 x 16B chunks), chunk ^= (row & 7).
extern __shared__ __align__(1024) uint8_t g_smem[];

DINL void issue_stage(uint32_t sb, int stage, int kblk,
                      const __half* gA0, const __half* gB0,
                      int arow0, uint32_t asw) {
    const uint32_t sa = sb + (uint32_t)stage * STAGE_BYTES;
    const uint32_t sA = sa + (uint32_t)arow0 * 128 + asw;
    const uint32_t sB = sa + A_ST + (uint32_t)arow0 * 128 + asw;
    const __half* ga = gA0 + kblk * BK;
    const __half* gb = gB0 + kblk * BK;
    // 256 threads x 8 chunks = 32 rows/pass; A 128 rows (4 passes), B 128 rows (4 passes)
#pragma unroll
    for (int j = 0; j < 4; ++j)
        cp16(sA + j * 32 * 128, ga + (size_t)j * 32 * KDIM);
#pragma unroll
    for (int j = 0; j < 4; ++j)
        cp16(sB + j * 32 * 128, gb + (size_t)j * 32 * KDIM);
    cp_commit();
}

__global__ void __launch_bounds__(THREADS, 2)
k_gemm(const __half* __restrict__ A, const __half* __restrict__ Bw,
       const float* __restrict__ bias, float* __restrict__ out) {
    const uint32_t sb = s2u(g_smem);
    const int tid  = threadIdx.x;
    const int wid  = tid >> 5;
    const int lane = tid & 31;
    const int m0 = blockIdx.y * BM;
    const int n0 = blockIdx.x * BN;

    const int wr = wid >> 2;       // 0..1  (M) -> 64 rows
    const int wc = wid & 3;        // 0..3  (N) -> 32 cols

    // cp.async thread mapping: 256 threads, 8 chunks/row; rows step by 32 (row&7 const)
    const int arow0 = tid >> 3;          // 0..31
    const int ach   = tid & 7;
    const uint32_t asw = (uint32_t)((ach ^ (arow0 & 7)) * 16);

    const __half* gA0 = A  + (size_t)(m0 + arow0) * KDIM + ach * 8;
    const __half* gB0 = Bw + (size_t)(n0 + arow0) * KDIM + ach * 8;

    // ---- prologue: fill STAGES-1 = 1 stage ----
#pragma unroll
    for (int s = 0; s < STAGES - 1; ++s)
        issue_stage(sb, s, s, gA0, gB0, arow0, asw);

    // ---- ldmatrix per-lane addressing ----
    const int a_r = (lane & 15);
    const int a_c = (lane >> 4);
    const int b_r = (lane & 7) + ((lane >> 4) << 3);
    const int b_c = (lane >> 3) & 1;

    float acc[4][4][4];
#pragma unroll
    for (int mi = 0; mi < 4; ++mi)
#pragma unroll
        for (int ni = 0; ni < 4; ++ni)
#pragma unroll
            for (int e = 0; e < 4; ++e) acc[mi][ni][e] = 0.f;

    for (int it = 0; it < NITER; ++it) {
        cp_wait<0>();               // prev iter's prefetch
        __syncthreads();

        if (it + STAGES - 1 < NITER)
            issue_stage(sb, (it + STAGES - 1) % STAGES, it + STAGES - 1,
                        gA0, gB0, arow0, asw);

        const uint32_t sa = sb + (uint32_t)(it % STAGES) * STAGE_BYTES;

#pragma unroll
        for (int ks = 0; ks < 4; ++ks) {
            uint32_t af[4][4], bf[2][4];
#pragma unroll
            for (int mi = 0; mi < 4; ++mi) {
                int row = wr * 64 + mi * 16 + a_r;
                int ch  = (ks * 2 + a_c) ^ (row & 7);
                ldsm4(af[mi][0], af[mi][1], af[mi][2], af[mi][3],
                      sa + (uint32_t)row * 128 + (uint32_t)ch * 16);
            }
#pragma unroll
            for (int nj = 0; nj < 2; ++nj) {
                int row = wc * 32 + nj * 16 + b_r;
                int ch  = (ks * 2 + b_c) ^ (row & 7);
                ldsm4(bf[nj][0], bf[nj][1], bf[nj][2], bf[nj][3],
                      sa + A_ST + (uint32_t)row * 128 + (uint32_t)ch * 16);
            }
#pragma unroll
            for (int mi = 0; mi < 4; ++mi)
#pragma unroll
                for (int ni = 0; ni < 4; ++ni)
                    mma16816(acc[mi][ni], af[mi], &bf[ni >> 1][(ni & 1) * 2]);
        }
    }

    // ---- epilogue: bias + fp32 store ----
    const int mrow = lane >> 2;
    const int ncol = (lane & 3) * 2;
#pragma unroll
    for (int mi = 0; mi < 4; ++mi) {
#pragma unroll
        for (int ni = 0; ni < 4; ++ni) {
            int n = n0 + wc * 32 + ni * 8 + ncol;
            float2 b2 = *(const float2*)(bias + n);
            size_t m = (size_t)m0 + wr * 64 + mi * 16 + mrow;
            float2 v0 = { acc[mi][ni][0] + b2.x, acc[mi][ni][1] + b2.y };
            float2 v1 = { acc[mi][ni][2] + b2.x, acc[mi][ni][3] + b2.y };
            *(float2*)(out + m * NDIM + n)       = v0;
            *(float2*)(out + (m + 8) * NDIM + n) = v1;
        }
    }
}

// ---------------- host ----------------
extern "C" void kernel_launch(void* const* d_in, const int* in_sizes, int n_in,
                              void* d_out, int out_size) {
    (void)in_sizes; (void)n_in; (void)out_size;
    const float* x    = (const float*)d_in[0];
    const int*   qw   = (const int*)d_in[1];
    const int*   qz   = (const int*)d_in[2];
    const float* sc   = (const float*)d_in[3];
    const float* bias = (const float*)d_in[4];
    float* out = (float*)d_out;

    void* xh_p = nullptr; void* wt_p = nullptr;
    cudaGetSymbolAddress(&xh_p, g_Xh);
    cudaGetSymbolAddress(&wt_p, g_Wt);

    // 1) fused pre-pass: x->fp16 convert + GPTQ dequant/transpose
    k_prep<<<CVT_BLOCKS + DQ_BLOCKS, 256>>>(
        (const float4*)x, (__half2*)xh_p, qw, qz, sc, (__half*)wt_p);
    // 2) 2-stage BK=64 HMMA GEMM + bias, 128x128 tile, 2 CTAs/SM
    cudaFuncSetAttribute(k_gemm, cudaFuncAttributeMaxDynamicSharedMemorySize, SMEM_BYTES);
    k_gemm<<<dim3(NDIM / BN, MDIM / BM), THREADS, SMEM_BYTES>>>(
        (const __half*)xh_p, (const __half*)wt_p, bias, out);
}

// round 16
// speedup vs baseline: 1.0160x; 1.0021x over previous
#include <cuda_runtime.h>
#include <cuda_fp16.h>
#include <cstdint>
#include <cstddef>

#define DINL __device__ __forceinline__

// ---------------- problem constants ----------------
constexpr int MDIM = 8192;   // B*S
constexpr int NDIM = 4096;   // OUT_FEATURES
constexpr int KDIM = 4096;   // IN_FEATURES

// ---------------- GEMM tiling (sized for 2 CTAs/SM) ----------------
constexpr int BM = 128;
constexpr int BN = 128;
constexpr int BK = 64;                       // halves; 128 B per smem row
constexpr int STAGES = 2;
constexpr int NITER = KDIM / BK;             // 64
constexpr int THREADS = 256;                 // 8 warps: 2 (M) x 4 (N), warp tile 64x32

constexpr uint32_t A_ST = BM * BK * 2;       // 16 KB
constexpr uint32_t B_ST = BN * BK * 2;       // 16 KB
constexpr uint32_t STAGE_BYTES = A_ST + B_ST;            // 32 KB
constexpr uint32_t SMEM_BYTES  = STAGES * STAGE_BYTES;   // 64 KB -> 2 CTAs/SM

// ---------------- scratch (device globals: allocation-rule-safe) ----------------
__device__ __align__(1024) __half g_Xh[(size_t)MDIM * KDIM];  // x fp16, [M,K] row-major
__device__ __align__(1024) __half g_Wt[(size_t)NDIM * KDIM];  // W^T fp16, [N,K] row-major

// ---------------- PTX helpers ----------------
DINL uint32_t s2u(const void* p) {
    uint32_t a;
    asm("{ .reg .u64 t; cvta.to.shared.u64 t, %1; cvt.u32.u64 %0, t; }" : "=r"(a) : "l"(p));
    return a;
}
DINL void cp16(uint32_t saddr, const void* gaddr) {
    asm volatile("cp.async.cg.shared.global [%0], [%1], 16;" :: "r"(saddr), "l"(gaddr));
}
DINL void cp_commit() { asm volatile("cp.async.commit_group;" ::: "memory"); }
template <int N> DINL void cp_wait() {
    asm volatile("cp.async.wait_group %0;" :: "n"(N) : "memory");
}
DINL void ldsm4(uint32_t& r0, uint32_t& r1, uint32_t& r2, uint32_t& r3, uint32_t a) {
    asm volatile("ldmatrix.sync.aligned.m8n8.x4.shared.b16 {%0,%1,%2,%3}, [%4];"
                 : "=r"(r0), "=r"(r1), "=r"(r2), "=r"(r3) : "r"(a));
}
DINL void mma16816(float* d, const uint32_t* a, const uint32_t* b) {
    asm volatile(
        "mma.sync.aligned.m16n8k16.row.col.f32.f16.f16.f32 "
        "{%0,%1,%2,%3}, {%4,%5,%6,%7}, {%8,%9}, {%0,%1,%2,%3};"
        : "+f"(d[0]), "+f"(d[1]), "+f"(d[2]), "+f"(d[3])
        : "r"(a[0]), "r"(a[1]), "r"(a[2]), "r"(a[3]), "r"(b[0]), "r"(b[1]));
}

// ---------------- kernel 1: fused pre-pass ----------------
// Blocks [0, CVT_BLOCKS): x fp32 -> fp16 (2 x float4 per thread).
// Blocks [CVT_BLOCKS, CVT_BLOCKS + DQ_BLOCKS): GPTQ dequant + transpose.
constexpr size_t   CVT_QUADS  = (size_t)MDIM * KDIM / 4;            // float4 count
constexpr unsigned CVT_BLOCKS = (unsigned)(CVT_QUADS / 2 / 256);    // 16384
constexpr unsigned DQ_KB      = KDIM / 64;                          // 64
constexpr unsigned DQ_BLOCKS  = DQ_KB * (NDIM / 64);                // 4096

__global__ void __launch_bounds__(256)
k_prep(const float4* __restrict__ x, __half2* __restrict__ xh,
       const int* __restrict__ qw, const int* __restrict__ qz,
       const float* __restrict__ sc, __half* __restrict__ wt) {
    const int t = threadIdx.x;

    if (blockIdx.x < CVT_BLOCKS) {
        // ---- phase A: fp32 -> fp16 convert ----
        size_t i = (size_t)blockIdx.x * 256 + t;
        float4 v0 = x[i];
        float4 v1 = x[i + CVT_QUADS / 2];
        xh[2 * i]                       = __floats2half2_rn(v0.x, v0.y);
        xh[2 * i + 1]                   = __floats2half2_rn(v0.z, v0.w);
        xh[2 * (i + CVT_QUADS / 2)]     = __floats2half2_rn(v1.x, v1.y);
        xh[2 * (i + CVT_QUADS / 2) + 1] = __floats2half2_rn(v1.z, v1.w);
        return;
    }

    // ---- phase B: GPTQ dequant + transpose ----
    // qweight [K/8, N] int32 (8 nibbles along K), qzeros [G, N/8] int32 (8
    // nibbles along N), scales [G, N] fp32.
    // Output: g_Wt[n][k] = scales[g][n] * (q - (z+1)) in fp16.
    const unsigned bid = blockIdx.x - CVT_BLOCKS;
    const int k0 = (int)(bid % DQ_KB) * 64;
    const int n0 = (int)(bid / DQ_KB) * 64;
    const int g  = k0 >> 7;                 // GROUPSIZE=128: 64-wide k-tile inside one group

    __shared__ int   sQ[8][64];
    __shared__ float sS[64];
    __shared__ float sZ[64];

    for (int i = t; i < 512; i += 256) {
        int r = i >> 6, c = i & 63;
        sQ[r][c] = qw[(size_t)(k0 / 8 + r) * NDIM + n0 + c];
    }
    if (t < 64) {
        int n = n0 + t;
        sS[t] = sc[(size_t)g * NDIM + n];
        unsigned z = ((unsigned)qz[(size_t)g * (NDIM / 8) + (n >> 3)] >> ((n & 7) * 4)) & 0xFu;
        sZ[t] = (float)(z + 1u);
    }
    __syncthreads();

    int ni = t >> 2, kq = t & 3;            // 64 n-rows x 4 k-quarters of 16
    float s = sS[ni], zp = sZ[ni];
    __half2 o[8];
#pragma unroll
    for (int j = 0; j < 2; j++) {
        unsigned packed = (unsigned)sQ[kq * 2 + j][ni];
#pragma unroll
        for (int b = 0; b < 4; b++) {
            float q0 = (float)(packed & 0xFu); packed >>= 4;
            float q1 = (float)(packed & 0xFu); packed >>= 4;
            o[j * 4 + b] = __floats2half2_rn(s * (q0 - zp), s * (q1 - zp));
        }
    }
    float4* dst = (float4*)(wt + (size_t)(n0 + ni) * KDIM + k0 + kq * 16);
    dst[0] = *(float4*)&o[0];
    dst[1] = *(float4*)&o[4];
}

// ---------------- kernel 2: 2-stage HMMA GEMM, 2 CTAs/SM ----------------
// A = g_Xh [M,K] row-major, B = g_Wt [N,K] row-major ("col" operand), C fp32.
// smem per stage: A then B; rows of 128B (8 x 16B chunks), chunk ^= (row & 7).
extern __shared__ __align__(1024) uint8_t g_smem[];

DINL void issue_stage(uint32_t sb, int stage, int kblk,
                      const __half* gA0, const __half* gB0,
                      int arow0, uint32_t asw) {
    const uint32_t sa = sb + (uint32_t)stage * STAGE_BYTES;
    const uint32_t sA = sa + (uint32_t)arow0 * 128 + asw;
    const uint32_t sB = sa + A_ST + (uint32_t)arow0 * 128 + asw;
    const __half* ga = gA0 + kblk * BK;
    const __half* gb = gB0 + kblk * BK;
    // 256 threads x 8 chunks = 32 rows/pass; A 128 rows (4 passes), B 128 rows (4 passes)
#pragma unroll
    for (int j = 0; j < 4; ++j)
        cp16(sA + j * 32 * 128, ga + (size_t)j * 32 * KDIM);
#pragma unroll
    for (int j = 0; j < 4; ++j)
        cp16(sB + j * 32 * 128, gb + (size_t)j * 32 * KDIM);
    cp_commit();
}

__global__ void __launch_bounds__(THREADS, 2)
k_gemm(const __half* __restrict__ A, const __half* __restrict__ Bw,
       const float* __restrict__ bias, float* __restrict__ out) {
    const uint32_t sb = s2u(g_smem);
    const int tid  = threadIdx.x;
    const int wid  = tid >> 5;
    const int lane = tid & 31;
    const int m0 = blockIdx.y * BM;
    const int n0 = blockIdx.x * BN;

    const int wr = wid >> 2;       // 0..1  (M) -> 64 rows
    const int wc = wid & 3;        // 0..3  (N) -> 32 cols

    // cp.async thread mapping: 256 threads, 8 chunks/row; rows step by 32 (row&7 const)
    const int arow0 = tid >> 3;          // 0..31
    const int ach   = tid & 7;
    const uint32_t asw = (uint32_t)((ach ^ (arow0 & 7)) * 16);

    const __half* gA0 = A  + (size_t)(m0 + arow0) * KDIM + ach * 8;
    const __half* gB0 = Bw + (size_t)(n0 + arow0) * KDIM + ach * 8;

    // ---- prologue: fill STAGES-1 = 1 stage ----
#pragma unroll
    for (int s = 0; s < STAGES - 1; ++s)
        issue_stage(sb, s, s, gA0, gB0, arow0, asw);

    // ---- ldmatrix per-lane addressing ----
    const int a_r = (lane & 15);
    const int a_c = (lane >> 4);
    const int b_r = (lane & 7) + ((lane >> 4) << 3);
    const int b_c = (lane >> 3) & 1;

    float acc[4][4][4];
#pragma unroll
    for (int mi = 0; mi < 4; ++mi)
#pragma unroll
        for (int ni = 0; ni < 4; ++ni)
#pragma unroll
            for (int e = 0; e < 4; ++e) acc[mi][ni][e] = 0.f;

    for (int it = 0; it < NITER; ++it) {
        cp_wait<0>();               // prev iter's prefetch
        __syncthreads();

        if (it + STAGES - 1 < NITER)
            issue_stage(sb, (it + STAGES - 1) % STAGES, it + STAGES - 1,
                        gA0, gB0, arow0, asw);

        const uint32_t sa = sb + (uint32_t)(it % STAGES) * STAGE_BYTES;

#pragma unroll
        for (int ks = 0; ks < 4; ++ks) {
            uint32_t af[4][4], bf[2][4];
#pragma unroll
            for (int mi = 0; mi < 4; ++mi) {
                int row = wr * 64 + mi * 16 + a_r;
                int ch  = (ks * 2 + a_c) ^ (row & 7);
                ldsm4(af[mi][0], af[mi][1], af[mi][2], af[mi][3],
                      sa + (uint32_t)row * 128 + (uint32_t)ch * 16);
            }
#pragma unroll
            for (int nj = 0; nj < 2; ++nj) {
                int row = wc * 32 + nj * 16 + b_r;
                int ch  = (ks * 2 + b_c) ^ (row & 7);
                ldsm4(bf[nj][0], bf[nj][1], bf[nj][2], bf[nj][3],
                      sa + A_ST + (uint32_t)row * 128 + (uint32_t)ch * 16);
            }
#pragma unroll
            for (int mi = 0; mi < 4; ++mi)
#pragma unroll
                for (int ni = 0; ni < 4; ++ni)
                    mma16816(acc[mi][ni], af[mi], &bf[ni >> 1][(ni & 1) * 2]);
        }
    }

    // ---- epilogue: bias + fp32 store ----
    const int mrow = lane >> 2;
    const int ncol = (lane & 3) * 2;
#pragma unroll
    for (int mi = 0; mi < 4; ++mi) {
#pragma unroll
        for (int ni = 0; ni < 4; ++ni) {
            int n = n0 + wc * 32 + ni * 8 + ncol;
            float2 b2 = *(const float2*)(bias + n);
            size_t m = (size_t)m0 + wr * 64 + mi * 16 + mrow;
            float2 v0 = { acc[mi][ni][0] + b2.x, acc[mi][ni][1] + b2.y };
            float2 v1 = { acc[mi][ni][2] + b2.x, acc[mi][ni][3] + b2.y };
            *(float2*)(out + m * NDIM + n)       = v0;
            *(float2*)(out + (m + 8) * NDIM + n) = v1;
        }
    }
}

// ---------------- host ----------------
extern "C" void kernel_launch(void* const* d_in, const int* in_sizes, int n_in,
                              void* d_out, int out_size) {
    (void)in_sizes; (void)n_in; (void)out_size;
    const float* x    = (const float*)d_in[0];
    const int*   qw   = (const int*)d_in[1];
    const int*   qz   = (const int*)d_in[2];
    const float* sc   = (const float*)d_in[3];
    const float* bias = (const float*)d_in[4];
    float* out = (float*)d_out;

    void* xh_p = nullptr; void* wt_p = nullptr;
    cudaGetSymbolAddress(&xh_p, g_Xh);
    cudaGetSymbolAddress(&wt_p, g_Wt);

    // 1) fused pre-pass: x->fp16 convert + GPTQ dequant/transpose
    k_prep<<<CVT_BLOCKS + DQ_BLOCKS, 256>>>(
        (const float4*)x, (__half2*)xh_p, qw, qz, sc, (__half*)wt_p);
    // 2) 2-stage BK=64 HMMA GEMM + bias, 128x128 tile, 2 CTAs/SM
    cudaFuncSetAttribute(k_gemm, cudaFuncAttributeMaxDynamicSharedMemorySize, SMEM_BYTES);
    k_gemm<<<dim3(NDIM / BN, MDIM / BM), THREADS, SMEM_BYTES>>>(
        (const __half*)xh_p, (const __half*)wt_p, bias, out);
}